// round 9
// baseline (speedup 1.0000x reference)
#include <cuda_runtime.h>
#include <cuda_bf16.h>

// LengthRegulator: B=16, T=512, D=384, target_len=4096, fp32.
// out[b, t, :] = x[b, idx(b,t), :], idx = searchsorted_right(cumsum(max(dur,1)), t),
// clamped to T-1; zero where t >= total(b).
//
// R5: R3 structure +
//  - warp handles 8 consecutive rows; reload x only when idx changes
//    (avg run length of idx ~7.6 -> ~2 distinct loads per 8 rows, -35-40% L1 work)
//  - __launch_bounds__(256, 8) -> <=32 regs, 2048 threads/SM (100% occ target)

namespace {

constexpr int B  = 16;
constexpr int T  = 512;
constexpr int D  = 384;
constexpr int TL = 4096;
constexpr int D4 = D / 4;        // 96 float4 per row
constexpr int ROWS = 64;         // output rows per block
constexpr int THREADS = 256;
constexpr int ROWS_PER_WARP = ROWS / (THREADS / 32);  // 8

__global__ __launch_bounds__(THREADS, 8)
void length_regulator_kernel(const float* __restrict__ x,
                             const int* __restrict__ durations,
                             float* __restrict__ out)
{
    __shared__ int s_cum[T];
    __shared__ int s_warp[8];
    __shared__ int s_idx[ROWS];   // source row per output row, -1 => zeros

    const int b    = blockIdx.y;
    const int tid  = threadIdx.x;
    const int lane = tid & 31;
    const int w    = tid >> 5;

    // ---- inclusive scan of max(dur,1) over T=512, 2 elements per thread ----
    const int2 dp = reinterpret_cast<const int2*>(durations + b * T)[tid];
    const int d0 = (dp.x < 1) ? 1 : dp.x;
    const int d1 = (dp.y < 1) ? 1 : dp.y;

    int v = d0 + d1;                        // pair sum
    #pragma unroll
    for (int o = 1; o < 32; o <<= 1) {
        int n = __shfl_up_sync(0xffffffffu, v, o);
        if (lane >= o) v += n;
    }
    if (lane == 31) s_warp[w] = v;
    __syncthreads();
    if (w == 0 && lane < 8) {
        int wv = s_warp[lane];
        #pragma unroll
        for (int o = 1; o < 8; o <<= 1) {
            int n = __shfl_up_sync(0x000000ffu, wv, o);
            if (lane >= o) wv += n;
        }
        s_warp[lane] = wv;
    }
    __syncthreads();
    const int base = (w > 0) ? s_warp[w - 1] : 0;
    const int c1 = base + v;                // cum at element 2*tid+1 (inclusive)
    s_cum[2 * tid]     = c1 - d1;           // cum at element 2*tid
    s_cum[2 * tid + 1] = c1;
    __syncthreads();

    const int total = s_cum[T - 1];
    const int t0 = blockIdx.x * ROWS;

    // ---- binary search (searchsorted right) for this block's 64 rows ----
    if (tid < ROWS) {
        const int t = t0 + tid;
        int lo = 0, hi = T;                  // first j with cum[j] > t
        while (lo < hi) {
            int mid = (lo + hi) >> 1;
            if (s_cum[mid] <= t) lo = mid + 1; else hi = mid;
        }
        int idx = (lo < T - 1) ? lo : (T - 1);
        s_idx[tid] = (t < total) ? idx : -1;
    }
    __syncthreads();

    // ---- hot loop: warp w owns rows [w*8, w*8+8); 3 float4 per lane per row.
    //      idx has long runs -> reload registers only when idx changes. ----
    const float4* __restrict__ xb =
        reinterpret_cast<const float4*>(x) + (size_t)b * T * D4;
    float4* __restrict__ ob =
        reinterpret_cast<float4*>(out) + ((size_t)b * TL + t0) * D4;

    const int r0 = w * ROWS_PER_WARP;
    int prev = -2;
    float4 v0, v1, v2;

    #pragma unroll
    for (int k = 0; k < ROWS_PER_WARP; ++k) {
        const int r   = r0 + k;
        const int idx = s_idx[r];            // broadcast LDS, warp-uniform
        if (idx != prev) {                   // warp-uniform branch
            if (idx >= 0) {
                const float4* __restrict__ xrow = xb + (size_t)idx * D4 + lane;
                v0 = xrow[0];
                v1 = xrow[32];
                v2 = xrow[64];
            } else {
                v0 = v1 = v2 = make_float4(0.f, 0.f, 0.f, 0.f);
            }
            prev = idx;
        }
        float4* __restrict__ orow = ob + (size_t)r * D4 + lane;
        orow[0]  = v0;
        orow[32] = v1;
        orow[64] = v2;
    }
}

} // namespace

extern "C" void kernel_launch(void* const* d_in, const int* in_sizes, int n_in,
                              void* d_out, int out_size)
{
    const float* x         = (const float*)d_in[0];
    const int*   durations = (const int*)d_in[1];
    float*       out       = (float*)d_out;

    dim3 grid(TL / ROWS, B);   // (64, 16)
    length_regulator_kernel<<<grid, THREADS>>>(x, durations, out);
}

// round 12
// speedup vs baseline: 1.3466x; 1.3466x over previous
#include <cuda_runtime.h>
#include <cuda_bf16.h>

// LengthRegulator: B=16, T=512, D=384, target_len=4096, fp32.
// out[b, t, :] = x[b, idx(b,t), :], idx = searchsorted_right(cumsum(max(dur,1)), t),
// clamped to T-1; zero where t >= total(b).
//
// R11: back to the known-good R3 structure (async-bulk path abandoned after two
// unexplained runtime faults). New: software-pipelined hot loop — loads for row
// k+1 issue before stores of row k (double-buffered), doubling per-warp MLP.
//  - 256-thread blocks, 32 rows/block, grid (128,16)=2048 blocks
//  - __launch_bounds__(256, 5): <=48 regs, room for 2x row buffers, no spills

namespace {

constexpr int B  = 16;
constexpr int T  = 512;
constexpr int D  = 384;
constexpr int TL = 4096;
constexpr int D4 = D / 4;        // 96 float4 per row
constexpr int ROWS = 32;         // output rows per block
constexpr int THREADS = 256;
constexpr int ROWS_PER_WARP = ROWS / (THREADS / 32);  // 4

__global__ __launch_bounds__(THREADS, 5)
void length_regulator_kernel(const float* __restrict__ x,
                             const int* __restrict__ durations,
                             float* __restrict__ out)
{
    __shared__ int s_cum[T];
    __shared__ int s_warp[8];
    __shared__ int s_idx[ROWS];   // source row per output row, -1 => zeros

    const int b    = blockIdx.y;
    const int tid  = threadIdx.x;
    const int lane = tid & 31;
    const int w    = tid >> 5;

    // ---- inclusive scan of max(dur,1) over T=512, 2 elements per thread ----
    const int2 dp = reinterpret_cast<const int2*>(durations + b * T)[tid];
    const int d0 = (dp.x < 1) ? 1 : dp.x;
    const int d1 = (dp.y < 1) ? 1 : dp.y;

    int v = d0 + d1;                        // pair sum
    #pragma unroll
    for (int o = 1; o < 32; o <<= 1) {
        int n = __shfl_up_sync(0xffffffffu, v, o);
        if (lane >= o) v += n;
    }
    if (lane == 31) s_warp[w] = v;
    __syncthreads();
    if (w == 0 && lane < 8) {
        int wv = s_warp[lane];
        #pragma unroll
        for (int o = 1; o < 8; o <<= 1) {
            int n = __shfl_up_sync(0x000000ffu, wv, o);
            if (lane >= o) wv += n;
        }
        s_warp[lane] = wv;
    }
    __syncthreads();
    const int base = (w > 0) ? s_warp[w - 1] : 0;
    const int c1 = base + v;                // cum at element 2*tid+1 (inclusive)
    s_cum[2 * tid]     = c1 - d1;           // cum at element 2*tid
    s_cum[2 * tid + 1] = c1;
    __syncthreads();

    const int total = s_cum[T - 1];
    const int t0 = blockIdx.x * ROWS;

    // ---- binary search (searchsorted right) for this block's 32 rows ----
    if (tid < ROWS) {
        const int t = t0 + tid;
        int lo = 0, hi = T;                  // first j with cum[j] > t
        while (lo < hi) {
            int mid = (lo + hi) >> 1;
            if (s_cum[mid] <= t) lo = mid + 1; else hi = mid;
        }
        int idx = (lo < T - 1) ? lo : (T - 1);
        s_idx[tid] = (t < total) ? idx : -1;
    }
    __syncthreads();

    // ---- hot loop: warp w owns rows [w*4, w*4+4); 3 float4 per lane per row.
    //      Software pipeline: load row k+1 before storing row k (2x MLP). ----
    const float4* __restrict__ xb =
        reinterpret_cast<const float4*>(x) + (size_t)b * T * D4;
    float4* __restrict__ ob =
        reinterpret_cast<float4*>(out) + ((size_t)b * TL + t0) * D4;

    const float4 zero4 = make_float4(0.f, 0.f, 0.f, 0.f);
    const int r0 = w * ROWS_PER_WARP;

    // fetch indices for all 4 rows up front
    int idxs[ROWS_PER_WARP];
    #pragma unroll
    for (int k = 0; k < ROWS_PER_WARP; ++k) idxs[k] = s_idx[r0 + k];

    // prologue: load row 0
    float4 c0 = zero4, c1v = zero4, c2 = zero4;
    if (idxs[0] >= 0) {
        const float4* __restrict__ xr = xb + (size_t)idxs[0] * D4 + lane;
        c0 = xr[0]; c1v = xr[32]; c2 = xr[64];
    }

    #pragma unroll
    for (int k = 0; k < ROWS_PER_WARP; ++k) {
        // issue next row's loads before this row's stores
        float4 n0 = zero4, n1 = zero4, n2 = zero4;
        if (k + 1 < ROWS_PER_WARP) {
            const int nidx = idxs[k + 1];
            if (nidx >= 0) {
                const float4* __restrict__ xr = xb + (size_t)nidx * D4 + lane;
                n0 = xr[0]; n1 = xr[32]; n2 = xr[64];
            }
        }

        float4* __restrict__ orow = ob + (size_t)(r0 + k) * D4 + lane;
        orow[0]  = c0;
        orow[32] = c1v;
        orow[64] = c2;

        c0 = n0; c1v = n1; c2 = n2;
    }
}

} // namespace

extern "C" void kernel_launch(void* const* d_in, const int* in_sizes, int n_in,
                              void* d_out, int out_size)
{
    const float* x         = (const float*)d_in[0];
    const int*   durations = (const int*)d_in[1];
    float*       out       = (float*)d_out;

    dim3 grid(TL / ROWS, B);   // (128, 16)
    length_regulator_kernel<<<grid, THREADS>>>(x, durations, out);
}

// round 13
// speedup vs baseline: 1.3484x; 1.0014x over previous
#include <cuda_runtime.h>
#include <cuda_bf16.h>

// LengthRegulator: B=16, T=512, D=384, target_len=4096, fp32.
// out[b, t, :] = x[b, idx(b,t), :], idx = searchsorted_right(cumsum(max(dur,1)), t),
// clamped to T-1; zero where t >= total(b).
//
// R12: INVERSE (run-length) expansion — cut L2/LTS bytes, the real limiter.
//  - warp owns source row j: loads it ONCE (3 LDG.128), stores it dur[j] times
//    to the contiguous output run [cum[j-1], min(cum[j], TL)). No searchsorted.
//  - reads through L2: 100MB -> 12.6MB; total LTS traffic 200 -> 113MB.
//  - tail rows [total, TL) zeroed by fixed per-block candidate slices
//    (rows >= T always, since total >= T); warps early-exit below total.
//  - grid (64, 16), 256 threads, 8 source rows per block (1 per warp).

namespace {

constexpr int B  = 16;
constexpr int T  = 512;
constexpr int D  = 384;
constexpr int TL = 4096;
constexpr int D4 = D / 4;            // 96 float4 per row
constexpr int THREADS = 256;
constexpr int WARPS = THREADS / 32;  // 8
constexpr int SRC_PER_BLOCK = WARPS; // 8 source rows per block
constexpr int BLOCKS_X = T / SRC_PER_BLOCK;            // 64
constexpr int TAIL_PER_BLOCK = (TL - T) / BLOCKS_X;    // 56
constexpr int TAIL_PER_WARP = TAIL_PER_BLOCK / WARPS;  // 7

__global__ __launch_bounds__(THREADS, 6)
void length_regulator_kernel(const float* __restrict__ x,
                             const int* __restrict__ durations,
                             float* __restrict__ out)
{
    __shared__ int s_cum[T];
    __shared__ int s_wscan[8];

    const int b    = blockIdx.y;
    const int tid  = threadIdx.x;
    const int lane = tid & 31;
    const int w    = tid >> 5;

    // ---- inclusive scan of max(dur,1) over T=512, 2 elements per thread ----
    const int2 dp = reinterpret_cast<const int2*>(durations + b * T)[tid];
    const int d0 = (dp.x < 1) ? 1 : dp.x;
    const int d1 = (dp.y < 1) ? 1 : dp.y;

    int v = d0 + d1;
    #pragma unroll
    for (int o = 1; o < 32; o <<= 1) {
        int n = __shfl_up_sync(0xffffffffu, v, o);
        if (lane >= o) v += n;
    }
    if (lane == 31) s_wscan[w] = v;
    __syncthreads();
    if (w == 0 && lane < 8) {
        int wv = s_wscan[lane];
        #pragma unroll
        for (int o = 1; o < 8; o <<= 1) {
            int n = __shfl_up_sync(0x000000ffu, wv, o);
            if (lane >= o) wv += n;
        }
        s_wscan[lane] = wv;
    }
    __syncthreads();
    const int base = (w > 0) ? s_wscan[w - 1] : 0;
    const int c1 = base + v;
    s_cum[2 * tid]     = c1 - d1;
    s_cum[2 * tid + 1] = c1;
    __syncthreads();

    const int total = s_cum[T - 1];

    float* __restrict__ ob = out + (size_t)b * TL * D;

    // ---- expansion: warp w owns source row j ----
    const int j = blockIdx.x * SRC_PER_BLOCK + w;
    const int start = (j == 0) ? 0 : s_cum[j - 1];
    const int end   = s_cum[j];
    const int end_c = (end < TL) ? end : TL;

    if (start < end_c) {
        const float4* __restrict__ xr =
            reinterpret_cast<const float4*>(x) + ((size_t)b * T + j) * D4 + lane;
        const float4 v0 = xr[0];
        const float4 v1 = xr[32];
        const float4 v2 = xr[64];

        float4* __restrict__ orow =
            reinterpret_cast<float4*>(ob) + (size_t)start * D4 + lane;
        for (int t = start; t < end_c; ++t) {
            orow[0]  = v0;
            orow[32] = v1;
            orow[64] = v2;
            orow += D4;
        }
    }

    // ---- tail zeroing: fixed candidate slice, rows >= T (total >= T always) ----
    if (total < TL) {
        const int cbase = T + blockIdx.x * TAIL_PER_BLOCK + w * TAIL_PER_WARP;
        const float4 z4 = make_float4(0.f, 0.f, 0.f, 0.f);
        #pragma unroll
        for (int q = 0; q < TAIL_PER_WARP; ++q) {
            const int r = cbase + q;          // r <= TL-1 by construction
            if (r >= total) {
                float4* __restrict__ orow =
                    reinterpret_cast<float4*>(ob) + (size_t)r * D4 + lane;
                orow[0]  = z4;
                orow[32] = z4;
                orow[64] = z4;
            }
        }
    }
}

} // namespace

extern "C" void kernel_launch(void* const* d_in, const int* in_sizes, int n_in,
                              void* d_out, int out_size)
{
    const float* x         = (const float*)d_in[0];
    const int*   durations = (const int*)d_in[1];
    float*       out       = (float*)d_out;

    dim3 grid(BLOCKS_X, B);   // (64, 16)
    length_regulator_kernel<<<grid, THREADS>>>(x, durations, out);
}

// round 14
// speedup vs baseline: 1.4827x; 1.0995x over previous
#include <cuda_runtime.h>
#include <cuda_bf16.h>

// LengthRegulator: B=16, T=512, D=384, target_len=4096, fp32.
// out[b, t, :] = x[b, idx(b,t), :], idx = searchsorted_right(cumsum(max(dur,1)), t),
// clamped to T-1; zero where t >= total(b).
//
// R13: R12 (inverse run-length expansion, reads-once) +
//  - __launch_bounds__(256, 8): whole 1024-block grid resident in ONE wave
//  - 2x-unrolled run store loop (denser issue)
//  - st.global.cs on output stores (evict-first; output is write-once)

namespace {

constexpr int B  = 16;
constexpr int T  = 512;
constexpr int D  = 384;
constexpr int TL = 4096;
constexpr int D4 = D / 4;            // 96 float4 per row
constexpr int THREADS = 256;
constexpr int WARPS = THREADS / 32;  // 8
constexpr int SRC_PER_BLOCK = WARPS; // 8 source rows per block
constexpr int BLOCKS_X = T / SRC_PER_BLOCK;            // 64
constexpr int TAIL_PER_BLOCK = (TL - T) / BLOCKS_X;    // 56
constexpr int TAIL_PER_WARP = TAIL_PER_BLOCK / WARPS;  // 7

__device__ __forceinline__ void stcs4(float4* p, float4 v) {
    asm volatile("st.global.cs.v4.f32 [%0], {%1, %2, %3, %4};"
                 :: "l"(p), "f"(v.x), "f"(v.y), "f"(v.z), "f"(v.w) : "memory");
}

__global__ __launch_bounds__(THREADS, 8)
void length_regulator_kernel(const float* __restrict__ x,
                             const int* __restrict__ durations,
                             float* __restrict__ out)
{
    __shared__ int s_cum[T];
    __shared__ int s_wscan[8];

    const int b    = blockIdx.y;
    const int tid  = threadIdx.x;
    const int lane = tid & 31;
    const int w    = tid >> 5;

    // ---- inclusive scan of max(dur,1) over T=512, 2 elements per thread ----
    const int2 dp = reinterpret_cast<const int2*>(durations + b * T)[tid];
    const int d0 = (dp.x < 1) ? 1 : dp.x;
    const int d1 = (dp.y < 1) ? 1 : dp.y;

    int v = d0 + d1;
    #pragma unroll
    for (int o = 1; o < 32; o <<= 1) {
        int n = __shfl_up_sync(0xffffffffu, v, o);
        if (lane >= o) v += n;
    }
    if (lane == 31) s_wscan[w] = v;
    __syncthreads();
    if (w == 0 && lane < 8) {
        int wv = s_wscan[lane];
        #pragma unroll
        for (int o = 1; o < 8; o <<= 1) {
            int n = __shfl_up_sync(0x000000ffu, wv, o);
            if (lane >= o) wv += n;
        }
        s_wscan[lane] = wv;
    }
    __syncthreads();
    const int base = (w > 0) ? s_wscan[w - 1] : 0;
    const int c1 = base + v;
    s_cum[2 * tid]     = c1 - d1;
    s_cum[2 * tid + 1] = c1;
    __syncthreads();

    const int total = s_cum[T - 1];

    float* __restrict__ ob = out + (size_t)b * TL * D;

    // ---- expansion: warp w owns source row j; store its run [start, end_c) ----
    const int j = blockIdx.x * SRC_PER_BLOCK + w;
    const int start = (j == 0) ? 0 : s_cum[j - 1];
    const int end   = s_cum[j];
    const int end_c = (end < TL) ? end : TL;

    if (start < end_c) {
        const float4* __restrict__ xr =
            reinterpret_cast<const float4*>(x) + ((size_t)b * T + j) * D4 + lane;
        const float4 v0 = xr[0];
        const float4 v1 = xr[32];
        const float4 v2 = xr[64];

        float4* __restrict__ orow =
            reinterpret_cast<float4*>(ob) + (size_t)start * D4 + lane;
        int cnt = end_c - start;

        // 2x-unrolled store loop for denser issue
        while (cnt >= 2) {
            stcs4(orow + 0,        v0);
            stcs4(orow + 32,       v1);
            stcs4(orow + 64,       v2);
            stcs4(orow + D4 + 0,   v0);
            stcs4(orow + D4 + 32,  v1);
            stcs4(orow + D4 + 64,  v2);
            orow += 2 * D4;
            cnt  -= 2;
        }
        if (cnt) {
            stcs4(orow + 0,  v0);
            stcs4(orow + 32, v1);
            stcs4(orow + 64, v2);
        }
    }

    // ---- tail zeroing: fixed candidate slice, rows >= T (total >= T always) ----
    if (total < TL) {
        const int cbase = T + blockIdx.x * TAIL_PER_BLOCK + w * TAIL_PER_WARP;
        const float4 z4 = make_float4(0.f, 0.f, 0.f, 0.f);
        #pragma unroll
        for (int q = 0; q < TAIL_PER_WARP; ++q) {
            const int r = cbase + q;          // r <= TL-1 by construction
            if (r >= total) {
                float4* __restrict__ orow =
                    reinterpret_cast<float4*>(ob) + (size_t)r * D4 + lane;
                stcs4(orow + 0,  z4);
                stcs4(orow + 32, z4);
                stcs4(orow + 64, z4);
            }
        }
    }
}

} // namespace

extern "C" void kernel_launch(void* const* d_in, const int* in_sizes, int n_in,
                              void* d_out, int out_size)
{
    const float* x         = (const float*)d_in[0];
    const int*   durations = (const int*)d_in[1];
    float*       out       = (float*)d_out;

    dim3 grid(BLOCKS_X, B);   // (64, 16)
    length_regulator_kernel<<<grid, THREADS>>>(x, durations, out);
}